// round 9
// baseline (speedup 1.0000x reference)
#include <cuda_runtime.h>
#include <cuda_bf16.h>

#define N_NODES 100000
#define N_EDGES 1600000
#define IN_CH 128
#define HID_CH 64
#define OUT_CH 64

#define SCAN_CHUNK 1024
#define SCAN_BLOCKS ((N_NODES + SCAN_CHUNK - 1) / SCAN_CHUNK)   // 98

typedef unsigned long long ull;

// packed dual-fp32 FMA (Blackwell f32x2 pipe; PTX-only)
#define FMA2(d, a, b) asm("fma.rn.f32x2 %0, %1, %2, %0;" : "+l"(d) : "l"(a), "l"(b))

__device__ __forceinline__ float f2lo(ull v) { return __uint_as_float((unsigned)(v & 0xffffffffu)); }
__device__ __forceinline__ float f2hi(ull v) { return __uint_as_float((unsigned)(v >> 32)); }

// ---------------- scratch (device globals; device-code access ONLY) ---------
__device__ int   g_idx64;
__device__ int   g_row[N_EDGES];
__device__ int   g_col[N_EDGES];
__device__ int   g_csr[N_EDGES];            // source indices grouped by dst
__device__ int   g_deg[N_NODES];            // 1 + in-degree (self-loop incl.)
__device__ int   g_start[N_NODES + 1];      // CSR offsets (edges only)
__device__ int   g_cur[N_NODES];            // scatter cursors
__device__ int   g_bsum[SCAN_BLOCKS];
__device__ float g_dinv[N_NODES];
__device__ float g_hs [N_NODES * HID_CH];   // dinv-scaled features (msg source)
__device__ float g_acc[N_NODES * HID_CH];   // layer-1 aggregation result

// ---------------- edge-index dtype probe --------------------------------------
__global__ void probe_kernel(const void* ei) {
    __shared__ int ok;
    if (threadIdx.x == 0) ok = 1;
    __syncthreads();
    const long long* p = (const long long*)ei;
    for (int i = threadIdx.x; i < 1024; i += blockDim.x) {
        long long v = p[i];
        if (v < 0 || v >= N_NODES) ok = 0;
    }
    __syncthreads();
    if (threadIdx.x == 0) g_idx64 = ok;
}

__global__ void init_deg_kernel() {
    int i = blockIdx.x * blockDim.x + threadIdx.x;
    if (i < N_NODES) g_deg[i] = 1;   // self-loop
}

// fused: convert dtype + clamp + store row/col + degree histogram (one pass)
__global__ void convert_count_kernel(const void* ei) {
    int e = blockIdx.x * blockDim.x + threadIdx.x;
    if (e >= N_EDGES) return;
    long long r, c;
    if (g_idx64) {
        const long long* p = (const long long*)ei;
        r = p[e]; c = p[e + N_EDGES];
    } else {
        const int* p = (const int*)ei;
        r = p[e]; c = p[e + N_EDGES];
    }
    if (r < 0) r = 0; if (r >= N_NODES) r = N_NODES - 1;
    if (c < 0) c = 0; if (c >= N_NODES) c = N_NODES - 1;
    g_row[e] = (int)r;
    g_col[e] = (int)c;
    atomicAdd(&g_deg[(int)c], 1);
}

// ---------------- CSR build: scan + scatter -----------------------------------
__global__ void __launch_bounds__(256) scan1_kernel() {
    __shared__ int warp_sums[8];
    int b   = blockIdx.x;
    int tid = threadIdx.x;
    int base = b * SCAN_CHUNK + tid * 4;

    int v0 = 0, v1 = 0, v2 = 0, v3 = 0;
    if (base + 0 < N_NODES) v0 = g_deg[base + 0] - 1;
    if (base + 1 < N_NODES) v1 = g_deg[base + 1] - 1;
    if (base + 2 < N_NODES) v2 = g_deg[base + 2] - 1;
    if (base + 3 < N_NODES) v3 = g_deg[base + 3] - 1;
    int tsum = v0 + v1 + v2 + v3;

    int lane = tid & 31, wid = tid >> 5;
    int s = tsum;
    #pragma unroll
    for (int off = 1; off < 32; off <<= 1) {
        int t = __shfl_up_sync(0xffffffffu, s, off);
        if (lane >= off) s += t;
    }
    if (lane == 31) warp_sums[wid] = s;
    __syncthreads();
    if (tid == 0) {
        int acc = 0;
        #pragma unroll
        for (int j = 0; j < 8; j++) { int t = warp_sums[j]; warp_sums[j] = acc; acc += t; }
        g_bsum[b] = acc;
    }
    __syncthreads();

    int excl = warp_sums[wid] + (s - tsum);
    if (base + 0 < N_NODES) g_start[base + 0] = excl; excl += v0;
    if (base + 1 < N_NODES) g_start[base + 1] = excl; excl += v1;
    if (base + 2 < N_NODES) g_start[base + 2] = excl; excl += v2;
    if (base + 3 < N_NODES) g_start[base + 3] = excl;
}

__global__ void scan2_kernel() {
    if (threadIdx.x == 0 && blockIdx.x == 0) {
        int acc = 0;
        for (int j = 0; j < SCAN_BLOCKS; j++) { int t = g_bsum[j]; g_bsum[j] = acc; acc += t; }
    }
}

// scan3 + dinv fused
__global__ void scan3_kernel() {
    int i = blockIdx.x * blockDim.x + threadIdx.x;
    if (i < N_NODES) {
        int v = g_start[i] + g_bsum[i / SCAN_CHUNK];
        g_start[i] = v;
        g_cur[i]   = v;
        g_dinv[i]  = rsqrtf((float)g_deg[i]);
    }
    if (i == 0) g_start[N_NODES] = N_EDGES;
}

__global__ void scatter_kernel() {
    int e = blockIdx.x * blockDim.x + threadIdx.x;
    if (e >= N_EDGES) return;
    int c = g_col[e];
    int pos = atomicAdd(&g_cur[c], 1);
    g_csr[pos] = g_row[e];
}

// ---------------- layer-1 GEMM (f32x2 packed): hs = dinv * (x @ W1) ----------
// 128 threads, 32 rows/block. Thread computes 4 rows x 4 cols.
// acc packed over column pairs; x duplicated (v,v) in transposed smem layout.
// dynamic smem: Wp[128*64]f | xd[128][32]float2 | xs[32][129]f  = 82048 B
#define G1_SMEM (IN_CH*HID_CH*4 + IN_CH*32*8 + 32*129*4)
__global__ void __launch_bounds__(128) gemm1_kernel(
    const float* __restrict__ x, const float* __restrict__ W1)
{
    extern __shared__ float smem[];
    float* Wp = smem;                              // 128x64 row-major (pairs via LDS.64)
    float* xd = smem + IN_CH * HID_CH;             // float2[k][r] duplicated
    float* xs = smem + IN_CH * HID_CH + IN_CH * 64;// [32][129] padded staging
    int tid = threadIdx.x;
    int row0 = blockIdx.x * 32;

    // stage W1 (8192 floats)
    for (int i = tid; i < (IN_CH * HID_CH) / 4; i += 128)
        ((float4*)Wp)[i] = ((const float4*)W1)[i];
    // stage x rows -> padded xs (coalesced global reads)
    for (int i = tid; i < 32 * (IN_CH / 4); i += 128) {
        int r  = i >> 5;
        int k4 = (i & 31) << 2;
        float4 v = ((const float4*)(x + (size_t)(row0 + r) * IN_CH))[k4 >> 2];
        float* p = xs + r * 129 + k4;
        p[0] = v.x; p[1] = v.y; p[2] = v.z; p[3] = v.w;
    }
    __syncthreads();
    // transpose + duplicate into xd (conflict-free both sides)
    for (int i = tid; i < 32 * IN_CH; i += 128) {
        int r = i & 31;
        int k = i >> 5;
        float v = xs[r * 129 + k];
        ((float2*)xd)[k * 32 + r] = make_float2(v, v);
    }
    __syncthreads();

    int cg = tid & 15;   // 16 col-groups of 4
    int rg = tid >> 4;   // 8 row-groups of 4
    const ull* Wp64 = (const ull*)Wp;
    const ull* xd64 = (const ull*)xd;

    ull a00 = 0, a01 = 0, a10 = 0, a11 = 0, a20 = 0, a21 = 0, a30 = 0, a31 = 0;
    #pragma unroll 4
    for (int k = 0; k < IN_CH; k++) {
        ull w0 = Wp64[k * 32 + cg * 2 + 0];
        ull w1 = Wp64[k * 32 + cg * 2 + 1];
        ull x0 = xd64[k * 32 + rg * 4 + 0];
        ull x1 = xd64[k * 32 + rg * 4 + 1];
        ull x2 = xd64[k * 32 + rg * 4 + 2];
        ull x3 = xd64[k * 32 + rg * 4 + 3];
        FMA2(a00, x0, w0); FMA2(a01, x0, w1);
        FMA2(a10, x1, w0); FMA2(a11, x1, w1);
        FMA2(a20, x2, w0); FMA2(a21, x2, w1);
        FMA2(a30, x3, w0); FMA2(a31, x3, w1);
    }
    ull pl[4] = {a00, a10, a20, a30};
    ull ph[4] = {a01, a11, a21, a31};
    #pragma unroll
    for (int j = 0; j < 4; j++) {
        int r = row0 + rg * 4 + j;
        float dv = g_dinv[r];
        float4 o = make_float4(f2lo(pl[j]) * dv, f2hi(pl[j]) * dv,
                               f2lo(ph[j]) * dv, f2hi(ph[j]) * dv);
        ((float4*)g_hs)[(size_t)r * 16 + cg] = o;
    }
}

// ---------------- gather-side aggregation (atomic-free) ----------------------
__global__ void __launch_bounds__(256) agg1_kernel()
{
    int t = blockIdx.x * blockDim.x + threadIdx.x;
    int n = t >> 4;
    int q = t & 15;
    if (n >= N_NODES) return;
    const float4* s4 = (const float4*)g_hs;

    float4 a = s4[(size_t)n * 16 + q];       // self-loop term
    float sx = a.x, sy = a.y, sz = a.z, sw = a.w;

    int i   = g_start[n];
    int end = g_start[n + 1];
    for (; i + 1 < end; i += 2) {
        int r0 = g_csr[i];
        int r1 = g_csr[i + 1];
        float4 v0 = s4[(size_t)r0 * 16 + q];
        float4 v1 = s4[(size_t)r1 * 16 + q];
        sx += v0.x; sy += v0.y; sz += v0.z; sw += v0.w;
        sx += v1.x; sy += v1.y; sz += v1.z; sw += v1.w;
    }
    if (i < end) {
        int r0 = g_csr[i];
        float4 v0 = s4[(size_t)r0 * 16 + q];
        sx += v0.x; sy += v0.y; sz += v0.z; sw += v0.w;
    }
    ((float4*)g_acc)[(size_t)n * 16 + q] = make_float4(sx, sy, sz, sw);
}

// layer-2 aggregation fused with final epilogue: out = dinv[n]*sum + b2
__global__ void __launch_bounds__(256) agg2_kernel(
    float* __restrict__ outp, const float* __restrict__ b2)
{
    int t = blockIdx.x * blockDim.x + threadIdx.x;
    int n = t >> 4;
    int q = t & 15;
    if (n >= N_NODES) return;
    const float4* s4 = (const float4*)g_hs;

    float4 a = s4[(size_t)n * 16 + q];
    float sx = a.x, sy = a.y, sz = a.z, sw = a.w;

    int i   = g_start[n];
    int end = g_start[n + 1];
    for (; i + 1 < end; i += 2) {
        int r0 = g_csr[i];
        int r1 = g_csr[i + 1];
        float4 v0 = s4[(size_t)r0 * 16 + q];
        float4 v1 = s4[(size_t)r1 * 16 + q];
        sx += v0.x; sy += v0.y; sz += v0.z; sw += v0.w;
        sx += v1.x; sy += v1.y; sz += v1.z; sw += v1.w;
    }
    if (i < end) {
        int r0 = g_csr[i];
        float4 v0 = s4[(size_t)r0 * 16 + q];
        sx += v0.x; sy += v0.y; sz += v0.z; sw += v0.w;
    }
    float dv = g_dinv[n];
    float4 bb = ((const float4*)b2)[q];
    float4 o;
    o.x = fmaf(dv, sx, bb.x);
    o.y = fmaf(dv, sy, bb.y);
    o.z = fmaf(dv, sz, bb.z);
    o.w = fmaf(dv, sw, bb.w);
    ((float4*)outp)[(size_t)n * 16 + q] = o;
}

// ---------------- layer-2 GEMM (f32x2): hs = dinv * (relu(dinv*acc+b1) @ W2) -
// static smem: Wp 16KB | xd 16KB | xs [32][65] 8.32KB
__global__ void __launch_bounds__(128) gemm2_kernel(
    const float* __restrict__ b1, const float* __restrict__ W2)
{
    __shared__ float Wp[HID_CH * OUT_CH];
    __shared__ float xd[HID_CH * 32 * 2];
    __shared__ float xs[32 * 65];
    int tid = threadIdx.x;
    int row0 = blockIdx.x * 32;

    for (int i = tid; i < (HID_CH * OUT_CH) / 4; i += 128)
        ((float4*)Wp)[i] = ((const float4*)W2)[i];
    // stage h1 = relu(dinv*acc + b1) into padded xs
    for (int i = tid; i < 32 * (HID_CH / 4); i += 128) {
        int r  = i >> 4;
        int k4 = (i & 15) << 2;
        int gr = row0 + r;
        float dv = g_dinv[gr];
        float4 av = ((const float4*)g_acc)[(size_t)gr * 16 + (k4 >> 2)];
        float4 bv = __ldg(((const float4*)b1) + (k4 >> 2));
        float* p = xs + r * 65 + k4;
        p[0] = fmaxf(fmaf(dv, av.x, bv.x), 0.f);
        p[1] = fmaxf(fmaf(dv, av.y, bv.y), 0.f);
        p[2] = fmaxf(fmaf(dv, av.z, bv.z), 0.f);
        p[3] = fmaxf(fmaf(dv, av.w, bv.w), 0.f);
    }
    __syncthreads();
    for (int i = tid; i < 32 * HID_CH; i += 128) {
        int r = i & 31;
        int k = i >> 5;
        float v = xs[r * 65 + k];
        ((float2*)xd)[k * 32 + r] = make_float2(v, v);
    }
    __syncthreads();

    int cg = tid & 15;
    int rg = tid >> 4;
    const ull* Wp64 = (const ull*)Wp;
    const ull* xd64 = (const ull*)xd;

    ull a00 = 0, a01 = 0, a10 = 0, a11 = 0, a20 = 0, a21 = 0, a30 = 0, a31 = 0;
    #pragma unroll 4
    for (int k = 0; k < HID_CH; k++) {
        ull w0 = Wp64[k * 32 + cg * 2 + 0];
        ull w1 = Wp64[k * 32 + cg * 2 + 1];
        ull x0 = xd64[k * 32 + rg * 4 + 0];
        ull x1 = xd64[k * 32 + rg * 4 + 1];
        ull x2 = xd64[k * 32 + rg * 4 + 2];
        ull x3 = xd64[k * 32 + rg * 4 + 3];
        FMA2(a00, x0, w0); FMA2(a01, x0, w1);
        FMA2(a10, x1, w0); FMA2(a11, x1, w1);
        FMA2(a20, x2, w0); FMA2(a21, x2, w1);
        FMA2(a30, x3, w0); FMA2(a31, x3, w1);
    }
    ull pl[4] = {a00, a10, a20, a30};
    ull ph[4] = {a01, a11, a21, a31};
    #pragma unroll
    for (int j = 0; j < 4; j++) {
        int r = row0 + rg * 4 + j;
        float dv = g_dinv[r];
        float4 o = make_float4(f2lo(pl[j]) * dv, f2hi(pl[j]) * dv,
                               f2lo(ph[j]) * dv, f2hi(ph[j]) * dv);
        ((float4*)g_hs)[(size_t)r * 16 + cg] = o;
    }
}

extern "C" void kernel_launch(void* const* d_in, const int* in_sizes, int n_in,
                              void* d_out, int out_size)
{
    // ---- identify inputs by element count ----
    const float* x  = nullptr;
    const void*  ei = nullptr;
    const float* W1 = nullptr;
    const float* b1 = nullptr;
    const float* W2 = nullptr;
    const float* b2 = nullptr;
    for (int i = 0; i < n_in; i++) {
        long long s = in_sizes[i];
        if      (s == (long long)N_NODES * IN_CH) x  = (const float*)d_in[i];
        else if (s == 2LL * N_EDGES)              ei = d_in[i];
        else if (s == (long long)IN_CH * HID_CH)  W1 = (const float*)d_in[i];
        else if (s == (long long)HID_CH * OUT_CH) W2 = (const float*)d_in[i];
        else if (s == HID_CH) { if (!b1) b1 = (const float*)d_in[i];
                                else     b2 = (const float*)d_in[i]; }
    }
    if (!x || !ei || !W1 || !b1 || !W2 || !b2) {
        x  = (const float*)d_in[0];
        ei = d_in[1];
        W1 = (const float*)d_in[2];
        b1 = (const float*)d_in[3];
        W2 = (const float*)d_in[4];
        b2 = (const float*)d_in[5];
    }
    float* outp = (float*)d_out;

    static int smem_set = 0;
    if (!smem_set) {
        cudaFuncSetAttribute(gemm1_kernel,
                             cudaFuncAttributeMaxDynamicSharedMemorySize, G1_SMEM);
        smem_set = 1;
    }

    // preprocessing
    probe_kernel<<<1, 256>>>(ei);
    init_deg_kernel<<<(N_NODES + 255) / 256, 256>>>();
    convert_count_kernel<<<(N_EDGES + 255) / 256, 256>>>(ei);
    scan1_kernel<<<SCAN_BLOCKS, 256>>>();
    scan2_kernel<<<1, 32>>>();
    scan3_kernel<<<(N_NODES + 255) / 256, 256>>>();
    scatter_kernel<<<(N_EDGES + 255) / 256, 256>>>();

    const int AGG_BLOCKS = (N_NODES * 16) / 256;   // 6250
    const int GEMM_BLOCKS = (N_NODES + 31) / 32;   // 3125

    // layer 1
    gemm1_kernel<<<GEMM_BLOCKS, 128, G1_SMEM>>>(x, W1);
    agg1_kernel<<<AGG_BLOCKS, 256>>>();

    // layer 2
    gemm2_kernel<<<GEMM_BLOCKS, 128>>>(b1, W2);
    agg2_kernel<<<AGG_BLOCKS, 256>>>(outp, b2);
}

// round 10
// speedup vs baseline: 1.2229x; 1.2229x over previous
#include <cuda_runtime.h>
#include <cuda_bf16.h>

#define N_NODES 100000
#define N_EDGES 1600000
#define IN_CH 128
#define HID_CH 64
#define OUT_CH 64

#define SCAN_CHUNK 1024
#define SCAN_BLOCKS ((N_NODES + SCAN_CHUNK - 1) / SCAN_CHUNK)   // 98

// ---------------- scratch (device globals; device-code access ONLY) ---------
__device__ int   g_idx64;
__device__ int   g_row[N_EDGES];
__device__ int   g_col[N_EDGES];
__device__ int   g_csr[N_EDGES];            // source indices grouped by dst
__device__ int   g_deg[N_NODES];            // 1 + in-degree (self-loop incl.)
__device__ int   g_start[N_NODES + 1];      // CSR offsets (edges only)
__device__ int   g_cur[N_NODES];            // scatter cursors
__device__ int   g_bsum[SCAN_BLOCKS];
__device__ float g_dinv[N_NODES];
__device__ float g_hs [N_NODES * HID_CH];   // dinv-scaled features (msg source)
__device__ float g_acc[N_NODES * HID_CH];   // layer-1 aggregation result

// ---------------- edge-index dtype probe --------------------------------------
__global__ void probe_kernel(const void* ei) {
    __shared__ int ok;
    if (threadIdx.x == 0) ok = 1;
    __syncthreads();
    const long long* p = (const long long*)ei;
    for (int i = threadIdx.x; i < 1024; i += blockDim.x) {
        long long v = p[i];
        if (v < 0 || v >= N_NODES) ok = 0;
    }
    __syncthreads();
    if (threadIdx.x == 0) g_idx64 = ok;
}

__global__ void init_deg_kernel() {
    int i = blockIdx.x * blockDim.x + threadIdx.x;
    if (i < N_NODES) g_deg[i] = 1;   // self-loop
}

// fused: convert dtype + clamp + store row/col + degree histogram (one pass)
__global__ void convert_count_kernel(const void* ei) {
    int e = blockIdx.x * blockDim.x + threadIdx.x;
    if (e >= N_EDGES) return;
    long long r, c;
    if (g_idx64) {
        const long long* p = (const long long*)ei;
        r = p[e]; c = p[e + N_EDGES];
    } else {
        const int* p = (const int*)ei;
        r = p[e]; c = p[e + N_EDGES];
    }
    if (r < 0) r = 0; if (r >= N_NODES) r = N_NODES - 1;
    if (c < 0) c = 0; if (c >= N_NODES) c = N_NODES - 1;
    g_row[e] = (int)r;
    g_col[e] = (int)c;
    atomicAdd(&g_deg[(int)c], 1);
}

// ---------------- CSR build: scan + scatter -----------------------------------
__global__ void __launch_bounds__(256) scan1_kernel() {
    __shared__ int warp_sums[8];
    int b   = blockIdx.x;
    int tid = threadIdx.x;
    int base = b * SCAN_CHUNK + tid * 4;

    int v0 = 0, v1 = 0, v2 = 0, v3 = 0;
    if (base + 0 < N_NODES) v0 = g_deg[base + 0] - 1;
    if (base + 1 < N_NODES) v1 = g_deg[base + 1] - 1;
    if (base + 2 < N_NODES) v2 = g_deg[base + 2] - 1;
    if (base + 3 < N_NODES) v3 = g_deg[base + 3] - 1;
    int tsum = v0 + v1 + v2 + v3;

    int lane = tid & 31, wid = tid >> 5;
    int s = tsum;
    #pragma unroll
    for (int off = 1; off < 32; off <<= 1) {
        int t = __shfl_up_sync(0xffffffffu, s, off);
        if (lane >= off) s += t;
    }
    if (lane == 31) warp_sums[wid] = s;
    __syncthreads();
    if (tid == 0) {
        int acc = 0;
        #pragma unroll
        for (int j = 0; j < 8; j++) { int t = warp_sums[j]; warp_sums[j] = acc; acc += t; }
        g_bsum[b] = acc;
    }
    __syncthreads();

    int excl = warp_sums[wid] + (s - tsum);
    if (base + 0 < N_NODES) g_start[base + 0] = excl; excl += v0;
    if (base + 1 < N_NODES) g_start[base + 1] = excl; excl += v1;
    if (base + 2 < N_NODES) g_start[base + 2] = excl; excl += v2;
    if (base + 3 < N_NODES) g_start[base + 3] = excl;
}

__global__ void scan2_kernel() {
    if (threadIdx.x == 0 && blockIdx.x == 0) {
        int acc = 0;
        for (int j = 0; j < SCAN_BLOCKS; j++) { int t = g_bsum[j]; g_bsum[j] = acc; acc += t; }
    }
}

// scan3 + dinv fused
__global__ void scan3_kernel() {
    int i = blockIdx.x * blockDim.x + threadIdx.x;
    if (i < N_NODES) {
        int v = g_start[i] + g_bsum[i / SCAN_CHUNK];
        g_start[i] = v;
        g_cur[i]   = v;
        g_dinv[i]  = rsqrtf((float)g_deg[i]);
    }
    if (i == 0) g_start[N_NODES] = N_EDGES;
}

__global__ void scatter_kernel() {
    int e = blockIdx.x * blockDim.x + threadIdx.x;
    if (e >= N_EDGES) return;
    int c = g_col[e];
    int pos = atomicAdd(&g_cur[c], 1);
    g_csr[pos] = g_row[e];
}

// ---------------- layer-1 GEMM (8x8 register tile): hs = dinv * (x @ W1) -----
// 128 threads, 128 rows/block. Thread tile = 8 rows x 8 cols.
// Per k: 8 scalar x-LDS + 2 LDS.128 w = 64B smem for 64 FMAs (1 B/FMA).
// x staged row-major with stride 133 (8*133 % 32 == 8 -> 4 warp row-groups
// hit distinct banks). W row-major [128][64].
#define XS1_STRIDE 133
#define G1_SMEM (IN_CH*HID_CH*4 + 128*XS1_STRIDE*4)   // 32768 + 68096 = 100864
__global__ void __launch_bounds__(128) gemm1_kernel(
    const float* __restrict__ x, const float* __restrict__ W1)
{
    extern __shared__ float smem[];
    float* Wp = smem;                       // [128][64]
    float* xs = smem + IN_CH * HID_CH;      // [128][133]
    int tid = threadIdx.x;
    int row0 = blockIdx.x * 128;

    for (int i = tid; i < (IN_CH * HID_CH) / 4; i += 128)
        ((float4*)Wp)[i] = ((const float4*)W1)[i];

    // stage 128 rows of x, coalesced (lanes sweep k within a row)
    for (int i = tid; i < 128 * 32; i += 128) {
        int r  = i >> 5;
        int k4 = (i & 31) * 4;
        int gr = row0 + r;
        float4 v = make_float4(0.f, 0.f, 0.f, 0.f);
        if (gr < N_NODES)
            v = ((const float4*)(x + (size_t)gr * IN_CH))[k4 >> 2];
        float* p = xs + r * XS1_STRIDE + k4;
        p[0] = v.x; p[1] = v.y; p[2] = v.z; p[3] = v.w;
    }
    __syncthreads();

    int cg = tid & 7;        // 8 col-groups of 8
    int rg = tid >> 3;       // 16 row-groups of 8
    const float* xrow = xs + rg * 8 * XS1_STRIDE;

    float acc[8][8];
    #pragma unroll
    for (int j = 0; j < 8; j++)
        #pragma unroll
        for (int c = 0; c < 8; c++) acc[j][c] = 0.f;

    #pragma unroll 4
    for (int k = 0; k < IN_CH; k++) {
        float4 wa = *(const float4*)&Wp[k * HID_CH + cg * 8];
        float4 wb = *(const float4*)&Wp[k * HID_CH + cg * 8 + 4];
        float xv[8];
        #pragma unroll
        for (int j = 0; j < 8; j++) xv[j] = xrow[j * XS1_STRIDE + k];
        #pragma unroll
        for (int j = 0; j < 8; j++) {
            acc[j][0] = fmaf(xv[j], wa.x, acc[j][0]);
            acc[j][1] = fmaf(xv[j], wa.y, acc[j][1]);
            acc[j][2] = fmaf(xv[j], wa.z, acc[j][2]);
            acc[j][3] = fmaf(xv[j], wa.w, acc[j][3]);
            acc[j][4] = fmaf(xv[j], wb.x, acc[j][4]);
            acc[j][5] = fmaf(xv[j], wb.y, acc[j][5]);
            acc[j][6] = fmaf(xv[j], wb.z, acc[j][6]);
            acc[j][7] = fmaf(xv[j], wb.w, acc[j][7]);
        }
    }

    #pragma unroll
    for (int j = 0; j < 8; j++) {
        int gr = row0 + rg * 8 + j;
        if (gr < N_NODES) {
            float dv = g_dinv[gr];
            float4 o0 = make_float4(acc[j][0]*dv, acc[j][1]*dv, acc[j][2]*dv, acc[j][3]*dv);
            float4 o1 = make_float4(acc[j][4]*dv, acc[j][5]*dv, acc[j][6]*dv, acc[j][7]*dv);
            ((float4*)g_hs)[(size_t)gr * 16 + cg * 2 + 0] = o0;
            ((float4*)g_hs)[(size_t)gr * 16 + cg * 2 + 1] = o1;
        }
    }
}

// ---------------- gather-side aggregation (atomic-free) ----------------------
__global__ void __launch_bounds__(256) agg1_kernel()
{
    int t = blockIdx.x * blockDim.x + threadIdx.x;
    int n = t >> 4;
    int q = t & 15;
    if (n >= N_NODES) return;
    const float4* s4 = (const float4*)g_hs;

    float4 a = s4[(size_t)n * 16 + q];       // self-loop term
    float sx = a.x, sy = a.y, sz = a.z, sw = a.w;

    int i   = g_start[n];
    int end = g_start[n + 1];
    for (; i + 1 < end; i += 2) {
        int r0 = g_csr[i];
        int r1 = g_csr[i + 1];
        float4 v0 = s4[(size_t)r0 * 16 + q];
        float4 v1 = s4[(size_t)r1 * 16 + q];
        sx += v0.x; sy += v0.y; sz += v0.z; sw += v0.w;
        sx += v1.x; sy += v1.y; sz += v1.z; sw += v1.w;
    }
    if (i < end) {
        int r0 = g_csr[i];
        float4 v0 = s4[(size_t)r0 * 16 + q];
        sx += v0.x; sy += v0.y; sz += v0.z; sw += v0.w;
    }
    ((float4*)g_acc)[(size_t)n * 16 + q] = make_float4(sx, sy, sz, sw);
}

// layer-2 aggregation fused with final epilogue: out = dinv[n]*sum + b2
__global__ void __launch_bounds__(256) agg2_kernel(
    float* __restrict__ outp, const float* __restrict__ b2)
{
    int t = blockIdx.x * blockDim.x + threadIdx.x;
    int n = t >> 4;
    int q = t & 15;
    if (n >= N_NODES) return;
    const float4* s4 = (const float4*)g_hs;

    float4 a = s4[(size_t)n * 16 + q];
    float sx = a.x, sy = a.y, sz = a.z, sw = a.w;

    int i   = g_start[n];
    int end = g_start[n + 1];
    for (; i + 1 < end; i += 2) {
        int r0 = g_csr[i];
        int r1 = g_csr[i + 1];
        float4 v0 = s4[(size_t)r0 * 16 + q];
        float4 v1 = s4[(size_t)r1 * 16 + q];
        sx += v0.x; sy += v0.y; sz += v0.z; sw += v0.w;
        sx += v1.x; sy += v1.y; sz += v1.z; sw += v1.w;
    }
    if (i < end) {
        int r0 = g_csr[i];
        float4 v0 = s4[(size_t)r0 * 16 + q];
        sx += v0.x; sy += v0.y; sz += v0.z; sw += v0.w;
    }
    float dv = g_dinv[n];
    float4 bb = ((const float4*)b2)[q];
    float4 o;
    o.x = fmaf(dv, sx, bb.x);
    o.y = fmaf(dv, sy, bb.y);
    o.z = fmaf(dv, sz, bb.z);
    o.w = fmaf(dv, sw, bb.w);
    ((float4*)outp)[(size_t)n * 16 + q] = o;
}

// ---------------- layer-2 GEMM (8x8): hs = dinv * (relu(dinv*acc+b1) @ W2) ---
#define XS2_STRIDE 69
#define G2_SMEM (HID_CH*OUT_CH*4 + 128*XS2_STRIDE*4)   // 16384 + 35328 = 51712
__global__ void __launch_bounds__(128) gemm2_kernel(
    const float* __restrict__ b1, const float* __restrict__ W2)
{
    extern __shared__ float smem[];
    float* Wp = smem;                       // [64][64]
    float* xs = smem + HID_CH * OUT_CH;     // [128][69]
    int tid = threadIdx.x;
    int row0 = blockIdx.x * 128;

    for (int i = tid; i < (HID_CH * OUT_CH) / 4; i += 128)
        ((float4*)Wp)[i] = ((const float4*)W2)[i];

    // stage h1 = relu(dinv*acc + b1), 128 rows
    for (int i = tid; i < 128 * 16; i += 128) {
        int r  = i >> 4;
        int k4 = (i & 15) * 4;
        int gr = row0 + r;
        float4 o = make_float4(0.f, 0.f, 0.f, 0.f);
        if (gr < N_NODES) {
            float dv = g_dinv[gr];
            float4 av = ((const float4*)g_acc)[(size_t)gr * 16 + (k4 >> 2)];
            float4 bv = __ldg(((const float4*)b1) + (k4 >> 2));
            o.x = fmaxf(fmaf(dv, av.x, bv.x), 0.f);
            o.y = fmaxf(fmaf(dv, av.y, bv.y), 0.f);
            o.z = fmaxf(fmaf(dv, av.z, bv.z), 0.f);
            o.w = fmaxf(fmaf(dv, av.w, bv.w), 0.f);
        }
        float* p = xs + r * XS2_STRIDE + k4;
        p[0] = o.x; p[1] = o.y; p[2] = o.z; p[3] = o.w;
    }
    __syncthreads();

    int cg = tid & 7;
    int rg = tid >> 3;
    const float* xrow = xs + rg * 8 * XS2_STRIDE;

    float acc[8][8];
    #pragma unroll
    for (int j = 0; j < 8; j++)
        #pragma unroll
        for (int c = 0; c < 8; c++) acc[j][c] = 0.f;

    #pragma unroll 4
    for (int k = 0; k < HID_CH; k++) {
        float4 wa = *(const float4*)&Wp[k * OUT_CH + cg * 8];
        float4 wb = *(const float4*)&Wp[k * OUT_CH + cg * 8 + 4];
        float xv[8];
        #pragma unroll
        for (int j = 0; j < 8; j++) xv[j] = xrow[j * XS2_STRIDE + k];
        #pragma unroll
        for (int j = 0; j < 8; j++) {
            acc[j][0] = fmaf(xv[j], wa.x, acc[j][0]);
            acc[j][1] = fmaf(xv[j], wa.y, acc[j][1]);
            acc[j][2] = fmaf(xv[j], wa.z, acc[j][2]);
            acc[j][3] = fmaf(xv[j], wa.w, acc[j][3]);
            acc[j][4] = fmaf(xv[j], wb.x, acc[j][4]);
            acc[j][5] = fmaf(xv[j], wb.y, acc[j][5]);
            acc[j][6] = fmaf(xv[j], wb.z, acc[j][6]);
            acc[j][7] = fmaf(xv[j], wb.w, acc[j][7]);
        }
    }

    #pragma unroll
    for (int j = 0; j < 8; j++) {
        int gr = row0 + rg * 8 + j;
        if (gr < N_NODES) {
            float dv = g_dinv[gr];
            float4 o0 = make_float4(acc[j][0]*dv, acc[j][1]*dv, acc[j][2]*dv, acc[j][3]*dv);
            float4 o1 = make_float4(acc[j][4]*dv, acc[j][5]*dv, acc[j][6]*dv, acc[j][7]*dv);
            ((float4*)g_hs)[(size_t)gr * 16 + cg * 2 + 0] = o0;
            ((float4*)g_hs)[(size_t)gr * 16 + cg * 2 + 1] = o1;
        }
    }
}

extern "C" void kernel_launch(void* const* d_in, const int* in_sizes, int n_in,
                              void* d_out, int out_size)
{
    // ---- identify inputs by element count ----
    const float* x  = nullptr;
    const void*  ei = nullptr;
    const float* W1 = nullptr;
    const float* b1 = nullptr;
    const float* W2 = nullptr;
    const float* b2 = nullptr;
    for (int i = 0; i < n_in; i++) {
        long long s = in_sizes[i];
        if      (s == (long long)N_NODES * IN_CH) x  = (const float*)d_in[i];
        else if (s == 2LL * N_EDGES)              ei = d_in[i];
        else if (s == (long long)IN_CH * HID_CH)  W1 = (const float*)d_in[i];
        else if (s == (long long)HID_CH * OUT_CH) W2 = (const float*)d_in[i];
        else if (s == HID_CH) { if (!b1) b1 = (const float*)d_in[i];
                                else     b2 = (const float*)d_in[i]; }
    }
    if (!x || !ei || !W1 || !b1 || !W2 || !b2) {
        x  = (const float*)d_in[0];
        ei = d_in[1];
        W1 = (const float*)d_in[2];
        b1 = (const float*)d_in[3];
        W2 = (const float*)d_in[4];
        b2 = (const float*)d_in[5];
    }
    float* outp = (float*)d_out;

    static int smem_set = 0;
    if (!smem_set) {
        cudaFuncSetAttribute(gemm1_kernel,
                             cudaFuncAttributeMaxDynamicSharedMemorySize, G1_SMEM);
        cudaFuncSetAttribute(gemm2_kernel,
                             cudaFuncAttributeMaxDynamicSharedMemorySize, G2_SMEM);
        smem_set = 1;
    }

    // preprocessing
    probe_kernel<<<1, 256>>>(ei);
    init_deg_kernel<<<(N_NODES + 255) / 256, 256>>>();
    convert_count_kernel<<<(N_EDGES + 255) / 256, 256>>>(ei);
    scan1_kernel<<<SCAN_BLOCKS, 256>>>();
    scan2_kernel<<<1, 32>>>();
    scan3_kernel<<<(N_NODES + 255) / 256, 256>>>();
    scatter_kernel<<<(N_EDGES + 255) / 256, 256>>>();

    const int AGG_BLOCKS  = (N_NODES * 16) / 256;    // 6250
    const int GEMM_BLOCKS = (N_NODES + 127) / 128;   // 782

    // layer 1
    gemm1_kernel<<<GEMM_BLOCKS, 128, G1_SMEM>>>(x, W1);
    agg1_kernel<<<AGG_BLOCKS, 256>>>();

    // layer 2
    gemm2_kernel<<<GEMM_BLOCKS, 128, G2_SMEM>>>(b1, W2);
    agg2_kernel<<<AGG_BLOCKS, 256>>>(outp, b2);
}

// round 11
// speedup vs baseline: 1.3098x; 1.0711x over previous
#include <cuda_runtime.h>
#include <cuda_bf16.h>

#define N_NODES 100000
#define N_EDGES 1600000
#define IN_CH 128
#define HID_CH 64
#define OUT_CH 64

#define SCAN_CHUNK 1024
#define SCAN_BLOCKS ((N_NODES + SCAN_CHUNK - 1) / SCAN_CHUNK)   // 98

// ---------------- scratch (device globals; device-code access ONLY) ---------
__device__ int   g_idx64;
__device__ int   g_row[N_EDGES];
__device__ int   g_col[N_EDGES];
__device__ int   g_csr[N_EDGES];            // source indices grouped by dst
__device__ int   g_deg[N_NODES];            // 1 + in-degree (self-loop incl.)
__device__ int   g_start[N_NODES + 1];      // CSR offsets (edges only)
__device__ int   g_cur[N_NODES];            // scatter cursors
__device__ int   g_bsum[SCAN_BLOCKS];
__device__ float g_dinv[N_NODES];
__device__ float g_hs [N_NODES * HID_CH];   // dinv-scaled features (msg source)
__device__ float g_acc[N_NODES * HID_CH];   // layer-1 aggregation result

// ---------------- probe (block 0) + deg init (all blocks), one launch --------
__global__ void probe_init_kernel(const void* ei) {
    int i = blockIdx.x * blockDim.x + threadIdx.x;
    if (i < N_NODES) g_deg[i] = 1;   // self-loop
    if (blockIdx.x == 0) {
        __shared__ int ok;
        if (threadIdx.x == 0) ok = 1;
        __syncthreads();
        const long long* p = (const long long*)ei;
        for (int j = threadIdx.x; j < 1024; j += blockDim.x) {
            long long v = p[j];
            if (v < 0 || v >= N_NODES) ok = 0;
        }
        __syncthreads();
        if (threadIdx.x == 0) g_idx64 = ok;
    }
}

// fused convert + clamp + degree histogram; 2 edges per thread (vector loads)
__global__ void convert_count_kernel(const void* ei) {
    int t = blockIdx.x * blockDim.x + threadIdx.x;
    int e = t * 2;
    if (e >= N_EDGES) return;
    long long r0, r1, c0, c1;
    if (g_idx64) {
        const longlong2* p = (const longlong2*)ei;
        longlong2 rr = p[t];
        longlong2 cc = p[(N_EDGES / 2) + t];
        r0 = rr.x; r1 = rr.y; c0 = cc.x; c1 = cc.y;
    } else {
        const int2* p = (const int2*)ei;
        int2 rr = p[t];
        int2 cc = p[(N_EDGES / 2) + t];
        r0 = rr.x; r1 = rr.y; c0 = cc.x; c1 = cc.y;
    }
    if (r0 < 0) r0 = 0; if (r0 >= N_NODES) r0 = N_NODES - 1;
    if (r1 < 0) r1 = 0; if (r1 >= N_NODES) r1 = N_NODES - 1;
    if (c0 < 0) c0 = 0; if (c0 >= N_NODES) c0 = N_NODES - 1;
    if (c1 < 0) c1 = 0; if (c1 >= N_NODES) c1 = N_NODES - 1;
    g_row[e]     = (int)r0;
    g_row[e + 1] = (int)r1;
    g_col[e]     = (int)c0;
    g_col[e + 1] = (int)c1;
    atomicAdd(&g_deg[(int)c0], 1);
    atomicAdd(&g_deg[(int)c1], 1);
}

// ---------------- CSR build: scan + scatter -----------------------------------
__global__ void __launch_bounds__(256) scan1_kernel() {
    __shared__ int warp_sums[8];
    int b   = blockIdx.x;
    int tid = threadIdx.x;
    int base = b * SCAN_CHUNK + tid * 4;

    int v0 = 0, v1 = 0, v2 = 0, v3 = 0;
    if (base + 0 < N_NODES) v0 = g_deg[base + 0] - 1;
    if (base + 1 < N_NODES) v1 = g_deg[base + 1] - 1;
    if (base + 2 < N_NODES) v2 = g_deg[base + 2] - 1;
    if (base + 3 < N_NODES) v3 = g_deg[base + 3] - 1;
    int tsum = v0 + v1 + v2 + v3;

    int lane = tid & 31, wid = tid >> 5;
    int s = tsum;
    #pragma unroll
    for (int off = 1; off < 32; off <<= 1) {
        int t = __shfl_up_sync(0xffffffffu, s, off);
        if (lane >= off) s += t;
    }
    if (lane == 31) warp_sums[wid] = s;
    __syncthreads();
    if (tid == 0) {
        int acc = 0;
        #pragma unroll
        for (int j = 0; j < 8; j++) { int t = warp_sums[j]; warp_sums[j] = acc; acc += t; }
        g_bsum[b] = acc;
    }
    __syncthreads();

    int excl = warp_sums[wid] + (s - tsum);
    if (base + 0 < N_NODES) g_start[base + 0] = excl; excl += v0;
    if (base + 1 < N_NODES) g_start[base + 1] = excl; excl += v1;
    if (base + 2 < N_NODES) g_start[base + 2] = excl; excl += v2;
    if (base + 3 < N_NODES) g_start[base + 3] = excl;
}

// parallel exclusive scan of the 98 block sums (1 block, 128 threads)
__global__ void scan2_kernel() {
    __shared__ int ws[4];
    int tid = threadIdx.x;
    int v = (tid < SCAN_BLOCKS) ? g_bsum[tid] : 0;
    int lane = tid & 31, w = tid >> 5;
    int s = v;
    #pragma unroll
    for (int off = 1; off < 32; off <<= 1) {
        int t = __shfl_up_sync(0xffffffffu, s, off);
        if (lane >= off) s += t;
    }
    if (lane == 31) ws[w] = s;
    __syncthreads();
    int add = 0;
    #pragma unroll
    for (int j = 0; j < 4; j++) if (j < w) add += ws[j];
    s += add;
    if (tid < SCAN_BLOCKS) g_bsum[tid] = s - v;   // exclusive
}

// scan3 + dinv fused
__global__ void scan3_kernel() {
    int i = blockIdx.x * blockDim.x + threadIdx.x;
    if (i < N_NODES) {
        int v = g_start[i] + g_bsum[i / SCAN_CHUNK];
        g_start[i] = v;
        g_cur[i]   = v;
        g_dinv[i]  = rsqrtf((float)g_deg[i]);
    }
    if (i == 0) g_start[N_NODES] = N_EDGES;
}

__global__ void scatter_kernel() {
    int e = blockIdx.x * blockDim.x + threadIdx.x;
    if (e >= N_EDGES) return;
    int c = g_col[e];
    int pos = atomicAdd(&g_cur[c], 1);
    g_csr[pos] = g_row[e];
}

// ---------------- layer-1 GEMM (8x8 register tile): hs = dinv * (x @ W1) -----
// Runs on a forked stream concurrent with the CSR scan/scatter chain; depends
// only on g_deg (dinv computed inline via rsqrtf).
#define XS1_STRIDE 133
#define G1_SMEM (IN_CH*HID_CH*4 + 128*XS1_STRIDE*4)   // 100864
__global__ void __launch_bounds__(128) gemm1_kernel(
    const float* __restrict__ x, const float* __restrict__ W1)
{
    extern __shared__ float smem[];
    float* Wp = smem;                       // [128][64]
    float* xs = smem + IN_CH * HID_CH;      // [128][133]
    int tid = threadIdx.x;
    int row0 = blockIdx.x * 128;

    for (int i = tid; i < (IN_CH * HID_CH) / 4; i += 128)
        ((float4*)Wp)[i] = ((const float4*)W1)[i];

    for (int i = tid; i < 128 * 32; i += 128) {
        int r  = i >> 5;
        int k4 = (i & 31) * 4;
        int gr = row0 + r;
        float4 v = make_float4(0.f, 0.f, 0.f, 0.f);
        if (gr < N_NODES)
            v = ((const float4*)(x + (size_t)gr * IN_CH))[k4 >> 2];
        float* p = xs + r * XS1_STRIDE + k4;
        p[0] = v.x; p[1] = v.y; p[2] = v.z; p[3] = v.w;
    }
    __syncthreads();

    int cg = tid & 7;
    int rg = tid >> 3;
    const float* xrow = xs + rg * 8 * XS1_STRIDE;

    float acc[8][8];
    #pragma unroll
    for (int j = 0; j < 8; j++)
        #pragma unroll
        for (int c = 0; c < 8; c++) acc[j][c] = 0.f;

    #pragma unroll 4
    for (int k = 0; k < IN_CH; k++) {
        float4 wa = *(const float4*)&Wp[k * HID_CH + cg * 8];
        float4 wb = *(const float4*)&Wp[k * HID_CH + cg * 8 + 4];
        float xv[8];
        #pragma unroll
        for (int j = 0; j < 8; j++) xv[j] = xrow[j * XS1_STRIDE + k];
        #pragma unroll
        for (int j = 0; j < 8; j++) {
            acc[j][0] = fmaf(xv[j], wa.x, acc[j][0]);
            acc[j][1] = fmaf(xv[j], wa.y, acc[j][1]);
            acc[j][2] = fmaf(xv[j], wa.z, acc[j][2]);
            acc[j][3] = fmaf(xv[j], wa.w, acc[j][3]);
            acc[j][4] = fmaf(xv[j], wb.x, acc[j][4]);
            acc[j][5] = fmaf(xv[j], wb.y, acc[j][5]);
            acc[j][6] = fmaf(xv[j], wb.z, acc[j][6]);
            acc[j][7] = fmaf(xv[j], wb.w, acc[j][7]);
        }
    }

    #pragma unroll
    for (int j = 0; j < 8; j++) {
        int gr = row0 + rg * 8 + j;
        if (gr < N_NODES) {
            float dv = rsqrtf((float)g_deg[gr]);   // inline dinv (needs only g_deg)
            float4 o0 = make_float4(acc[j][0]*dv, acc[j][1]*dv, acc[j][2]*dv, acc[j][3]*dv);
            float4 o1 = make_float4(acc[j][4]*dv, acc[j][5]*dv, acc[j][6]*dv, acc[j][7]*dv);
            ((float4*)g_hs)[(size_t)gr * 16 + cg * 2 + 0] = o0;
            ((float4*)g_hs)[(size_t)gr * 16 + cg * 2 + 1] = o1;
        }
    }
}

// ---------------- gather-side aggregation (atomic-free) ----------------------
__global__ void __launch_bounds__(256) agg1_kernel()
{
    int t = blockIdx.x * blockDim.x + threadIdx.x;
    int n = t >> 4;
    int q = t & 15;
    if (n >= N_NODES) return;
    const float4* s4 = (const float4*)g_hs;

    float4 a = s4[(size_t)n * 16 + q];       // self-loop term
    float sx = a.x, sy = a.y, sz = a.z, sw = a.w;

    int i   = g_start[n];
    int end = g_start[n + 1];
    for (; i + 1 < end; i += 2) {
        int r0 = g_csr[i];
        int r1 = g_csr[i + 1];
        float4 v0 = s4[(size_t)r0 * 16 + q];
        float4 v1 = s4[(size_t)r1 * 16 + q];
        sx += v0.x; sy += v0.y; sz += v0.z; sw += v0.w;
        sx += v1.x; sy += v1.y; sz += v1.z; sw += v1.w;
    }
    if (i < end) {
        int r0 = g_csr[i];
        float4 v0 = s4[(size_t)r0 * 16 + q];
        sx += v0.x; sy += v0.y; sz += v0.z; sw += v0.w;
    }
    ((float4*)g_acc)[(size_t)n * 16 + q] = make_float4(sx, sy, sz, sw);
}

// layer-2 aggregation fused with final epilogue: out = dinv[n]*sum + b2
__global__ void __launch_bounds__(256) agg2_kernel(
    float* __restrict__ outp, const float* __restrict__ b2)
{
    int t = blockIdx.x * blockDim.x + threadIdx.x;
    int n = t >> 4;
    int q = t & 15;
    if (n >= N_NODES) return;
    const float4* s4 = (const float4*)g_hs;

    float4 a = s4[(size_t)n * 16 + q];
    float sx = a.x, sy = a.y, sz = a.z, sw = a.w;

    int i   = g_start[n];
    int end = g_start[n + 1];
    for (; i + 1 < end; i += 2) {
        int r0 = g_csr[i];
        int r1 = g_csr[i + 1];
        float4 v0 = s4[(size_t)r0 * 16 + q];
        float4 v1 = s4[(size_t)r1 * 16 + q];
        sx += v0.x; sy += v0.y; sz += v0.z; sw += v0.w;
        sx += v1.x; sy += v1.y; sz += v1.z; sw += v1.w;
    }
    if (i < end) {
        int r0 = g_csr[i];
        float4 v0 = s4[(size_t)r0 * 16 + q];
        sx += v0.x; sy += v0.y; sz += v0.z; sw += v0.w;
    }
    float dv = g_dinv[n];
    float4 bb = ((const float4*)b2)[q];
    float4 o;
    o.x = fmaf(dv, sx, bb.x);
    o.y = fmaf(dv, sy, bb.y);
    o.z = fmaf(dv, sz, bb.z);
    o.w = fmaf(dv, sw, bb.w);
    ((float4*)outp)[(size_t)n * 16 + q] = o;
}

// ---------------- layer-2 GEMM (8x8): hs = dinv * (relu(dinv*acc+b1) @ W2) ---
#define XS2_STRIDE 69
#define G2_SMEM (HID_CH*OUT_CH*4 + 128*XS2_STRIDE*4)   // 51712
__global__ void __launch_bounds__(128) gemm2_kernel(
    const float* __restrict__ b1, const float* __restrict__ W2)
{
    extern __shared__ float smem[];
    float* Wp = smem;                       // [64][64]
    float* xs = smem + HID_CH * OUT_CH;     // [128][69]
    int tid = threadIdx.x;
    int row0 = blockIdx.x * 128;

    for (int i = tid; i < (HID_CH * OUT_CH) / 4; i += 128)
        ((float4*)Wp)[i] = ((const float4*)W2)[i];

    for (int i = tid; i < 128 * 16; i += 128) {
        int r  = i >> 4;
        int k4 = (i & 15) * 4;
        int gr = row0 + r;
        float4 o = make_float4(0.f, 0.f, 0.f, 0.f);
        if (gr < N_NODES) {
            float dv = g_dinv[gr];
            float4 av = ((const float4*)g_acc)[(size_t)gr * 16 + (k4 >> 2)];
            float4 bv = __ldg(((const float4*)b1) + (k4 >> 2));
            o.x = fmaxf(fmaf(dv, av.x, bv.x), 0.f);
            o.y = fmaxf(fmaf(dv, av.y, bv.y), 0.f);
            o.z = fmaxf(fmaf(dv, av.z, bv.z), 0.f);
            o.w = fmaxf(fmaf(dv, av.w, bv.w), 0.f);
        }
        float* p = xs + r * XS2_STRIDE + k4;
        p[0] = o.x; p[1] = o.y; p[2] = o.z; p[3] = o.w;
    }
    __syncthreads();

    int cg = tid & 7;
    int rg = tid >> 3;
    const float* xrow = xs + rg * 8 * XS2_STRIDE;

    float acc[8][8];
    #pragma unroll
    for (int j = 0; j < 8; j++)
        #pragma unroll
        for (int c = 0; c < 8; c++) acc[j][c] = 0.f;

    #pragma unroll 4
    for (int k = 0; k < HID_CH; k++) {
        float4 wa = *(const float4*)&Wp[k * OUT_CH + cg * 8];
        float4 wb = *(const float4*)&Wp[k * OUT_CH + cg * 8 + 4];
        float xv[8];
        #pragma unroll
        for (int j = 0; j < 8; j++) xv[j] = xrow[j * XS2_STRIDE + k];
        #pragma unroll
        for (int j = 0; j < 8; j++) {
            acc[j][0] = fmaf(xv[j], wa.x, acc[j][0]);
            acc[j][1] = fmaf(xv[j], wa.y, acc[j][1]);
            acc[j][2] = fmaf(xv[j], wa.z, acc[j][2]);
            acc[j][3] = fmaf(xv[j], wa.w, acc[j][3]);
            acc[j][4] = fmaf(xv[j], wb.x, acc[j][4]);
            acc[j][5] = fmaf(xv[j], wb.y, acc[j][5]);
            acc[j][6] = fmaf(xv[j], wb.z, acc[j][6]);
            acc[j][7] = fmaf(xv[j], wb.w, acc[j][7]);
        }
    }

    #pragma unroll
    for (int j = 0; j < 8; j++) {
        int gr = row0 + rg * 8 + j;
        if (gr < N_NODES) {
            float dv = g_dinv[gr];
            float4 o0 = make_float4(acc[j][0]*dv, acc[j][1]*dv, acc[j][2]*dv, acc[j][3]*dv);
            float4 o1 = make_float4(acc[j][4]*dv, acc[j][5]*dv, acc[j][6]*dv, acc[j][7]*dv);
            ((float4*)g_hs)[(size_t)gr * 16 + cg * 2 + 0] = o0;
            ((float4*)g_hs)[(size_t)gr * 16 + cg * 2 + 1] = o1;
        }
    }
}

extern "C" void kernel_launch(void* const* d_in, const int* in_sizes, int n_in,
                              void* d_out, int out_size)
{
    // ---- identify inputs by element count ----
    const float* x  = nullptr;
    const void*  ei = nullptr;
    const float* W1 = nullptr;
    const float* b1 = nullptr;
    const float* W2 = nullptr;
    const float* b2 = nullptr;
    for (int i = 0; i < n_in; i++) {
        long long s = in_sizes[i];
        if      (s == (long long)N_NODES * IN_CH) x  = (const float*)d_in[i];
        else if (s == 2LL * N_EDGES)              ei = d_in[i];
        else if (s == (long long)IN_CH * HID_CH)  W1 = (const float*)d_in[i];
        else if (s == (long long)HID_CH * OUT_CH) W2 = (const float*)d_in[i];
        else if (s == HID_CH) { if (!b1) b1 = (const float*)d_in[i];
                                else     b2 = (const float*)d_in[i]; }
    }
    if (!x || !ei || !W1 || !b1 || !W2 || !b2) {
        x  = (const float*)d_in[0];
        ei = d_in[1];
        W1 = (const float*)d_in[2];
        b1 = (const float*)d_in[3];
        W2 = (const float*)d_in[4];
        b2 = (const float*)d_in[5];
    }
    float* outp = (float*)d_out;

    static cudaStream_t sB = nullptr;
    static cudaEvent_t  evA = nullptr, evB = nullptr;
    if (!sB) {
        cudaStreamCreateWithFlags(&sB, cudaStreamNonBlocking);
        cudaEventCreateWithFlags(&evA, cudaEventDisableTiming);
        cudaEventCreateWithFlags(&evB, cudaEventDisableTiming);
        cudaFuncSetAttribute(gemm1_kernel,
                             cudaFuncAttributeMaxDynamicSharedMemorySize, G1_SMEM);
        cudaFuncSetAttribute(gemm2_kernel,
                             cudaFuncAttributeMaxDynamicSharedMemorySize, G2_SMEM);
    }

    const int AGG_BLOCKS  = (N_NODES * 16) / 256;    // 6250
    const int GEMM_BLOCKS = (N_NODES + 127) / 128;   // 782

    // preprocessing head (main stream)
    probe_init_kernel<<<(N_NODES + 255) / 256, 256>>>(ei);
    convert_count_kernel<<<(N_EDGES / 2 + 255) / 256, 256>>>(ei);

    // fork: gemm1 (needs only g_deg + x/W1) runs concurrent with CSR build
    cudaEventRecord(evA, 0);
    cudaStreamWaitEvent(sB, evA, 0);
    gemm1_kernel<<<GEMM_BLOCKS, 128, G1_SMEM, sB>>>(x, W1);
    cudaEventRecord(evB, sB);

    // CSR build (main stream)
    scan1_kernel<<<SCAN_BLOCKS, 256>>>();
    scan2_kernel<<<1, 128>>>();
    scan3_kernel<<<(N_NODES + 255) / 256, 256>>>();
    scatter_kernel<<<(N_EDGES + 255) / 256, 256>>>();

    // join: agg1 needs both gemm1 (g_hs) and scatter (g_csr/g_start)
    cudaStreamWaitEvent(0, evB, 0);
    agg1_kernel<<<AGG_BLOCKS, 256>>>();

    // layer 2 (serial dependency chain)
    gemm2_kernel<<<GEMM_BLOCKS, 128, G2_SMEM>>>(b1, W2);
    agg2_kernel<<<AGG_BLOCKS, 256>>>(outp, b2);
}